// round 10
// baseline (speedup 1.0000x reference)
#include <cuda_runtime.h>
#include <cstdint>

#define BB 8
#define CC 8
#define HH 512
#define WW 512
#define PLANE (HH*WW)                 // 262144
#define PIX   (BB*HH*WW)              // 2097152
#define NEL   (BB*CC*HH*WW)           // 16777216

#define TPB   64                      // threads per block (2 warps)
#define RPT   4                       // rows per thread
#define CPB   (TPB*4)                 // 256 cols per block
#define NBX   (WW/CPB)                // 2
#define NBY   (HH/RPT)                // 128
#define NBLK  (NBX*NBY*BB)            // 2048
#define SLOTS 3                       // cp.async row ring depth

__device__ double       g_acc;        // zero-init; reset by last block each run
__device__ unsigned int g_count;      // wraps to 0 via atomicInc

// sigmoid via single-MUFU tanh.approx: sigma(x) = 0.5 + 0.5*tanh(x/2)
__device__ __forceinline__ float sigt(float x) {
    float t;
    asm("tanh.approx.f32 %0, %1;" : "=f"(t) : "f"(0.5f * x));
    return fmaf(0.5f, t, 0.5f);
}
__device__ __forceinline__ float4 ld4(const float* __restrict__ p) {
    return *reinterpret_cast<const float4*>(p);
}
__device__ __forceinline__ float clog(float x) {
    return fmaxf(__logf(x), -100.0f);   // matches jnp.clip(log(x), -100)
}

// 16B async copy global->shared, predicated (group committed by caller)
__device__ __forceinline__ void cpa16(uint32_t dst, const float* __restrict__ src,
                                      bool p) {
    if (p)
        asm volatile("cp.async.cg.shared.global [%0], [%1], 16;"
                     :: "r"(dst), "l"(src));
}
#define CP_COMMIT() asm volatile("cp.async.commit_group;" ::: "memory")
#define CP_WAIT(n)  asm volatile("cp.async.wait_group %0;" :: "n"(n) : "memory")

// col w0-1 of same row/channel: left lane's a[3]; lane-0 fixup LDG (L2 hit)
__device__ __forceinline__ float getL(const float a[4], const float* __restrict__ g,
                                      bool ok, int lane) {
    float v = __shfl_up_sync(0xffffffffu, a[3], 1);
    if (lane == 0) v = ok ? sigt(__ldg(g)) : 0.0f;
    return v;
}
// col w0+4: right lane's a[0]; lane-31 fixup LDG
__device__ __forceinline__ float getR(const float a[4], const float* __restrict__ g,
                                      bool ok, int lane) {
    float v = __shfl_down_sync(0xffffffffu, a[0], 1);
    if (lane == 31) v = ok ? sigt(__ldg(g)) : 0.0f;
    return v;
}

// con_target bitmasks (4 px x 8 bits) + target bits packed into one u64
__device__ __forceinline__ unsigned long long build_mask(
        const float* __restrict__ cb, const float* __restrict__ tb) {
    unsigned m0 = 0, m1 = 0, m2 = 0, m3 = 0;
#pragma unroll
    for (int c = 0; c < 8; c++) {
        float4 t = ld4(cb + c * PLANE);
        m0 |= ((unsigned)(t.x > 0.5f)) << c;
        m1 |= ((unsigned)(t.y > 0.5f)) << c;
        m2 |= ((unsigned)(t.z > 0.5f)) << c;
        m3 |= ((unsigned)(t.w > 0.5f)) << c;
    }
    float4 tg = ld4(tb);
    unsigned t4 = (unsigned)(tg.x > 0.5f) | ((unsigned)(tg.y > 0.5f) << 1)
                | ((unsigned)(tg.z > 0.5f) << 2) | ((unsigned)(tg.w > 0.5f) << 3);
    return (unsigned long long)(m0 | (m1 << 8) | (m2 << 16) | (m3 << 24))
         | ((unsigned long long)t4 << 32);
}

// votes + loss terms for one row of a 4-pixel strip.
// Shm: ch5,6,7 sigmoids at row r-1; C: all 8 ch at row r; Sn: ch0,1,2 at row r+1.
__device__ __forceinline__ float row_votes(
    const float Shm[3][4], const float C[8][4], const float Sn[3][4],
    const float* __restrict__ px,
    bool wlo, bool whi, int lane, bool hmok, bool hpok,
    unsigned long long mp, int pass)
{
    float L7 = getL(Shm[2], px - WW + 7 * PLANE - 1, hmok && !wlo, lane);
    float R5 = getR(Shm[0], px - WW + 5 * PLANE + 4, hmok && !whi, lane);
    float L4 = getL(C[4],   px      + 4 * PLANE - 1, !wlo,         lane);
    float R3 = getR(C[3],   px      + 3 * PLANE + 4, !whi,         lane);
    float L2 = getL(Sn[2],  px + WW + 2 * PLANE - 1, hpok && !wlo, lane);
    float R0 = getR(Sn[0],  px + WW + 0 * PLANE + 4, hpok && !whi, lane);

    float accb = 0.0f, accp = 0.0f;
#pragma unroll
    for (int p = 0; p < 4; p++) {
        float nb[8];
        nb[0] = (p == 0) ? L7 : Shm[2][p == 0 ? 0 : p - 1];   // c7(r-1, w-1)
        nb[1] = Shm[1][p];                                    // c6(r-1, w)
        nb[2] = (p == 3) ? R5 : Shm[0][p == 3 ? 3 : p + 1];   // c5(r-1, w+1)
        nb[3] = (p == 0) ? L4 : C[4][p == 0 ? 0 : p - 1];     // c4(r,   w-1)
        nb[4] = (p == 3) ? R3 : C[3][p == 3 ? 3 : p + 1];     // c3(r,   w+1)
        nb[5] = (p == 0) ? L2 : Sn[2][p == 0 ? 0 : p - 1];    // c2(r+1, w-1)
        nb[6] = Sn[1][p];                                     // c1(r+1, w)
        nb[7] = (p == 3) ? R0 : Sn[0][p == 3 ? 3 : p + 1];    // c0(r+1, w+1)

        unsigned m = (unsigned)(mp >> (8 * p)) & 0xFFu;
        bool T = (mp >> (32 + p)) & 1ull;

        float pA0 = 1.f, pA1 = 1.f, pB0 = 1.f, pB1 = 1.f;
        float glo = 0.f, mn = 1e30f;
        int npen = 0;
#pragma unroll
        for (int k = 0; k < 8; k++) {
            float s = C[k][p];
            float v = s * nb[k];
            glo += v;
            mn = fminf(mn, v);
            bool t = (m >> k) & 1u;
            float A = t ? v : 1.0f - v;
            if (A == 0.0f) { npen++; A = 1.0f; }   // padded border: exact -100 later
            float Bv = t ? s : 1.0f - s;
            if (k < 4) { pA0 *= A; pB0 *= Bv; }
            else       { pA1 *= A; pB1 *= Bv; }
        }
        float bic = __logf(pA0) + __logf(pA1) - 100.0f * (float)npen;
        float co  = __logf(pB0) + __logf(pB1);
        accb += 0.2f * bic + 0.8f * co;

        float g = glo * 0.125f;
        float x;
        if (pass == 0) {
            x = T ? g : 1.0f - g;                        // bce_loss1
        } else {
            bool edge = (m != 0u) && (m != 255u);
            float de  = edge ? (1.0f - mn) : g;          // decouple map
            x = T ? de : 1.0f - de;
        }
        accp += clog(x);
    }
    return accb * (1.0f / (float)NEL) + accp * (1.0f / (float)PIX);
}

__global__ void __launch_bounds__(TPB, 8)
bicon_loss_kernel(const float* __restrict__ atts,
                  const float* __restrict__ dets,
                  const float* __restrict__ target,
                  const float* __restrict__ con,
                  float* __restrict__ out)
{
    __shared__ float4 ring[SLOTS][CC][TPB];        // 24 KB cp.async row ring
    __shared__ unsigned long long mk[RPT * TPB];   // 2 KB per-thread mask cache
    __shared__ float wsum[TPB / 32];

    const int tid  = threadIdx.x;
    const int lane = tid & 31;
    const int bid  = blockIdx.x;
    const int cpart = bid & (NBX - 1);
    const int band  = (bid / NBX) & (NBY - 1);
    const int b     = bid / (NBX * NBY);
    const int w0 = cpart * CPB + tid * 4;
    const int r0 = band * RPT;
    const bool wlo = (w0 == 0), whi = (w0 + 4 == WW);
    const bool lastband = (r0 + RPT >= HH);

    const size_t bst  = (size_t)CC * PLANE;
    const size_t soff = (size_t)r0 * WW + w0;   // strip offset within batch image

    // smem ring base addresses (per-thread private cells)
    uint32_t rbase = (uint32_t)__cvta_generic_to_shared(&ring[0][0][tid]);
#define RSLOT(s, c) (rbase + (uint32_t)(((s) * CC + (c)) * TPB * 16))

    // all RPT row masks up-front (36-LDG burst), cached in private smem slots
    {
        const float* cpx = con + (size_t)b * bst + soff;
        const float* tpx = target + (size_t)b * PLANE + soff;
#pragma unroll
        for (int i = 0; i < RPT; i++)
            mk[i * TPB + tid] = build_mask(cpx + i * WW, tpx + i * WW);
    }

    float contrib = 0.0f;

#pragma unroll 1
    for (int pass = 0; pass < 2; pass++) {
        const float* px = (pass ? dets : atts) + (size_t)b * bst + soff;

        CP_WAIT(0);   // ring reusable (prev pass leftovers are empty groups)

        // preloop prefetch: rows r0+1..r0+3 (all in-bounds; r0 <= HH-RPT)
#pragma unroll
        for (int j = 0; j < SLOTS; j++) {
#pragma unroll
            for (int c = 0; c < CC; c++)
                cpa16(RSLOT(j, c), px + (j + 1) * WW + c * PLANE, true);
            CP_COMMIT();
        }

        // prologue via LDG: row r0-1 ch5..7 (or zeros), row r0 all 8
        float Shm[3][4], C[8][4];
        if (r0 > 0) {
#pragma unroll
            for (int j = 0; j < 3; j++) {
                float4 x = ld4(px - WW + (5 + j) * PLANE);
                Shm[j][0] = sigt(x.x); Shm[j][1] = sigt(x.y);
                Shm[j][2] = sigt(x.z); Shm[j][3] = sigt(x.w);
            }
        } else {
#pragma unroll
            for (int j = 0; j < 3; j++)
#pragma unroll
                for (int p = 0; p < 4; p++) Shm[j][p] = 0.0f;
        }
#pragma unroll
        for (int c = 0; c < 8; c++) {
            float4 x = ld4(px + c * PLANE);
            C[c][0] = sigt(x.x); C[c][1] = sigt(x.y);
            C[c][2] = sigt(x.z); C[c][3] = sigt(x.w);
        }

        // fully-unrolled row loop; slot (i % SLOTS) holds row r0+i+1
#pragma unroll
        for (int i = 0; i < RPT; i++) {
            const int si = i % SLOTS;
            CP_WAIT(2);   // consumed slot's group retired

            float Sn[3][4];
            if (i == RPT - 1 && lastband) {
#pragma unroll
                for (int c = 0; c < 3; c++)
#pragma unroll
                    for (int p = 0; p < 4; p++) Sn[c][p] = 0.0f;
            } else {
#pragma unroll
                for (int c = 0; c < 3; c++) {
                    float4 x = ring[si][c][tid];
                    Sn[c][0] = sigt(x.x); Sn[c][1] = sigt(x.y);
                    Sn[c][2] = sigt(x.z); Sn[c][3] = sigt(x.w);
                }
            }

            unsigned long long mp = mk[i * TPB + tid];
            const bool hmok = (i > 0) || (r0 > 0);
            const bool hpok = (i < RPT - 1) || !lastband;

            contrib += row_votes(Shm, C, Sn, px + i * WW, wlo, whi, lane,
                                 hmok, hpok, mp, pass);

            if (i < RPT - 1) {
                // rotate: Shm <- C[5..7]; C <- [Sn | sigt(ring ch3..7)]
#pragma unroll
                for (int j = 0; j < 3; j++)
#pragma unroll
                    for (int p = 0; p < 4; p++) Shm[j][p] = C[5 + j][p];
#pragma unroll
                for (int c = 0; c < 3; c++)
#pragma unroll
                    for (int p = 0; p < 4; p++) C[c][p] = Sn[c][p];
#pragma unroll
                for (int c = 3; c < 8; c++) {
                    float4 x = ring[si][c][tid];
                    C[c][0] = sigt(x.x); C[c][1] = sigt(x.y);
                    C[c][2] = sigt(x.z); C[c][3] = sigt(x.w);
                }

                // prefetch row r0+i+4 into freed slot si (ch0..2 only when it's
                // the band's last Sn row); empty commit keeps group count static
                if (i + 4 == RPT) {
#pragma unroll
                    for (int c = 0; c < 3; c++)
                        cpa16(RSLOT(si, c), px + (i + 4) * WW + c * PLANE,
                              !lastband);
                } else if (i + 4 < RPT) {
#pragma unroll
                    for (int c = 0; c < CC; c++)
                        cpa16(RSLOT(si, c), px + (i + 4) * WW + c * PLANE, true);
                }
                CP_COMMIT();
            }
        }
    }

    // block reduction: warp shfl -> smem -> one double atomic per block
#pragma unroll
    for (int o = 16; o > 0; o >>= 1)
        contrib += __shfl_down_sync(0xFFFFFFFFu, contrib, o);
    if (lane == 0) wsum[tid >> 5] = contrib;
    __syncthreads();

    if (tid == 0) {
        float s = 0.0f;
#pragma unroll
        for (int i = 0; i < TPB / 32; i++) s += wsum[i];
        atomicAdd(&g_acc, (double)s);
        __threadfence();
        unsigned old = atomicInc(&g_count, NBLK - 1u);   // wraps to 0 on last
        if (old == NBLK - 1u) {
            unsigned long long raw =
                atomicExch((unsigned long long*)&g_acc, 0ULL);
            out[0] = -(float)__longlong_as_double(raw);
        }
    }
}

extern "C" void kernel_launch(void* const* d_in, const int* in_sizes, int n_in,
                              void* d_out, int out_size) {
    const float* atts   = (const float*)d_in[0];
    const float* dets   = (const float*)d_in[1];
    const float* target = (const float*)d_in[2];
    const float* con    = (const float*)d_in[3];
    float* out = (float*)d_out;

    bicon_loss_kernel<<<NBLK, TPB>>>(atts, dets, target, con, out);
}

// round 11
// speedup vs baseline: 1.0772x; 1.0772x over previous
#include <cuda_runtime.h>
#include <cstdint>

#define BB 8
#define CC 8
#define HH 512
#define WW 512
#define PLANE (HH*WW)                 // 262144
#define PIX   (BB*HH*WW)              // 2097152
#define NEL   (BB*CC*HH*WW)           // 16777216

#define TPB   64                      // threads per block (2 warps)
#define RPT   8                       // rows per thread
#define CPB   (TPB*4)                 // 256 cols per block
#define NBX   (WW/CPB)                // 2
#define NBY   (HH/RPT)                // 64
#define NBLK  (NBX*NBY*BB)            // 1024

__device__ double       g_acc;        // zero-init; reset by last block each run
__device__ unsigned int g_count;      // wraps to 0 via atomicInc

// sigmoid via single-MUFU tanh.approx: sigma(x) = 0.5 + 0.5*tanh(x/2)
__device__ __forceinline__ float sigt(float x) {
    float t;
    asm("tanh.approx.f32 %0, %1;" : "=f"(t) : "f"(0.5f * x));
    return fmaf(0.5f, t, 0.5f);
}
__device__ __forceinline__ float4 ld4(const float* __restrict__ p) {
    return *reinterpret_cast<const float4*>(p);
}
__device__ __forceinline__ float clog(float x) {
    return fmaxf(__logf(x), -100.0f);   // matches jnp.clip(log(x), -100)
}

// col w0-1 of same row/channel: left lane's a[3]; lane-0 fixup LDG
__device__ __forceinline__ float getL(const float a[4], const float* __restrict__ g,
                                      bool ok, int lane) {
    float v = __shfl_up_sync(0xffffffffu, a[3], 1);
    if (lane == 0) v = ok ? sigt(__ldg(g)) : 0.0f;
    return v;
}
// col w0+4: right lane's a[0]; lane-31 fixup LDG
__device__ __forceinline__ float getR(const float a[4], const float* __restrict__ g,
                                      bool ok, int lane) {
    float v = __shfl_down_sync(0xffffffffu, a[0], 1);
    if (lane == 31) v = ok ? sigt(__ldg(g)) : 0.0f;
    return v;
}

// con_target bitmasks (4 px x 8 bits) + target bits packed into one u64
__device__ __forceinline__ unsigned long long build_mask(
        const float* __restrict__ cb, const float* __restrict__ tb) {
    unsigned m0 = 0, m1 = 0, m2 = 0, m3 = 0;
#pragma unroll
    for (int c = 0; c < 8; c++) {
        float4 t = ld4(cb + c * PLANE);
        m0 |= ((unsigned)(t.x > 0.5f)) << c;
        m1 |= ((unsigned)(t.y > 0.5f)) << c;
        m2 |= ((unsigned)(t.z > 0.5f)) << c;
        m3 |= ((unsigned)(t.w > 0.5f)) << c;
    }
    float4 tg = ld4(tb);
    unsigned t4 = (unsigned)(tg.x > 0.5f) | ((unsigned)(tg.y > 0.5f) << 1)
                | ((unsigned)(tg.z > 0.5f) << 2) | ((unsigned)(tg.w > 0.5f) << 3);
    return (unsigned long long)(m0 | (m1 << 8) | (m2 << 16) | (m3 << 24))
         | ((unsigned long long)t4 << 32);
}

// votes + loss terms for one row of a 4-pixel strip.
// Shm: ch5,6,7 sigmoids at row r-1; C: all 8 ch at row r; Sn: ch0,1,2 at row r+1.
__device__ __forceinline__ float row_votes(
    const float Shm[3][4], const float C[8][4], const float Sn[3][4],
    const float* __restrict__ px,
    bool wlo, bool whi, int lane, bool hmok, bool hpok,
    unsigned long long mp, int pass)
{
    float L7 = getL(Shm[2], px - WW + 7 * PLANE - 1, hmok && !wlo, lane);
    float R5 = getR(Shm[0], px - WW + 5 * PLANE + 4, hmok && !whi, lane);
    float L4 = getL(C[4],   px      + 4 * PLANE - 1, !wlo,         lane);
    float R3 = getR(C[3],   px      + 3 * PLANE + 4, !whi,         lane);
    float L2 = getL(Sn[2],  px + WW + 2 * PLANE - 1, hpok && !wlo, lane);
    float R0 = getR(Sn[0],  px + WW + 0 * PLANE + 4, hpok && !whi, lane);

    float accb = 0.0f, accp = 0.0f;
#pragma unroll
    for (int p = 0; p < 4; p++) {
        float nb[8];
        nb[0] = (p == 0) ? L7 : Shm[2][p == 0 ? 0 : p - 1];   // c7(r-1, w-1)
        nb[1] = Shm[1][p];                                    // c6(r-1, w)
        nb[2] = (p == 3) ? R5 : Shm[0][p == 3 ? 3 : p + 1];   // c5(r-1, w+1)
        nb[3] = (p == 0) ? L4 : C[4][p == 0 ? 0 : p - 1];     // c4(r,   w-1)
        nb[4] = (p == 3) ? R3 : C[3][p == 3 ? 3 : p + 1];     // c3(r,   w+1)
        nb[5] = (p == 0) ? L2 : Sn[2][p == 0 ? 0 : p - 1];    // c2(r+1, w-1)
        nb[6] = Sn[1][p];                                     // c1(r+1, w)
        nb[7] = (p == 3) ? R0 : Sn[0][p == 3 ? 3 : p + 1];    // c0(r+1, w+1)

        unsigned m = (unsigned)(mp >> (8 * p)) & 0xFFu;
        bool T = (mp >> (32 + p)) & 1ull;

        // fast path: raw products, one log per side; exact fallback when the
        // product underflows/zeros (padded borders) — matches per-term clamp.
        float pA = 1.f, pB = 1.f, glo = 0.f, mn = 1e30f;
#pragma unroll
        for (int k = 0; k < 8; k++) {
            float s = C[k][p];
            float v = s * nb[k];
            glo += v;
            if (pass == 1) mn = fminf(mn, v);
            bool t = (m >> k) & 1u;
            pA *= t ? v : 1.0f - v;
            pB *= t ? s : 1.0f - s;
        }

        float bic, co;
        if (pA >= 1e-37f) {
            bic = __logf(pA);
        } else {                       // rare: border zeros / extreme tails
            bic = 0.0f;
#pragma unroll
            for (int k = 0; k < 8; k++) {
                float v = C[k][p] * nb[k];
                bool t = (m >> k) & 1u;
                bic += clog(t ? v : 1.0f - v);
            }
        }
        if (pB >= 1e-37f) {
            co = __logf(pB);
        } else {
            co = 0.0f;
#pragma unroll
            for (int k = 0; k < 8; k++) {
                float s = C[k][p];
                bool t = (m >> k) & 1u;
                co += clog(t ? s : 1.0f - s);
            }
        }
        accb += 0.2f * bic + 0.8f * co;

        float g = glo * 0.125f;
        float x;
        if (pass == 0) {
            x = T ? g : 1.0f - g;                        // bce_loss1
        } else {
            bool edge = (m != 0u) && (m != 255u);
            float de  = edge ? (1.0f - mn) : g;          // decouple map
            x = T ? de : 1.0f - de;
        }
        accp += clog(x);
    }
    return accb * (1.0f / (float)NEL) + accp * (1.0f / (float)PIX);
}

__global__ void __launch_bounds__(TPB, 8)
bicon_loss_kernel(const float* __restrict__ atts,
                  const float* __restrict__ dets,
                  const float* __restrict__ target,
                  const float* __restrict__ con,
                  float* __restrict__ out)
{
    __shared__ unsigned long long mk[RPT * TPB];   // 4 KB per-thread mask cache
    __shared__ float wsum[TPB / 32];

    const int tid  = threadIdx.x;
    const int lane = tid & 31;
    const int bid  = blockIdx.x;
    const int cpart = bid & (NBX - 1);
    const int band  = (bid / NBX) & (NBY - 1);
    const int b     = bid / (NBX * NBY);
    const int w0 = cpart * CPB + tid * 4;
    const int r0 = band * RPT;
    const bool wlo = (w0 == 0), whi = (w0 + 4 == WW);

    const size_t bst  = (size_t)CC * PLANE;
    const size_t soff = (size_t)r0 * WW + w0;   // strip offset within batch image

    float contrib = 0.0f;

#pragma unroll 1
    for (int pass = 0; pass < 2; pass++) {
        const float* px = (pass ? dets : atts) + (size_t)b * bst + soff;

        // prologue: row r0-1 channels 5..7; row r0 all 8
        float Shm[3][4];
        if (r0 > 0) {
#pragma unroll
            for (int j = 0; j < 3; j++) {
                float4 x = ld4(px - WW + (5 + j) * PLANE);
                Shm[j][0] = sigt(x.x); Shm[j][1] = sigt(x.y);
                Shm[j][2] = sigt(x.z); Shm[j][3] = sigt(x.w);
            }
        } else {
#pragma unroll
            for (int j = 0; j < 3; j++)
#pragma unroll
                for (int p = 0; p < 4; p++) Shm[j][p] = 0.0f;
        }
        float C[8][4];
#pragma unroll
        for (int c = 0; c < 8; c++) {
            float4 x = ld4(px + c * PLANE);
            C[c][0] = sigt(x.x); C[c][1] = sigt(x.y);
            C[c][2] = sigt(x.z); C[c][3] = sigt(x.w);
        }

        const float* cpx = con + (size_t)b * bst + soff;       // rolling con ptr
        const float* tpx = target + (size_t)b * PLANE + soff;  // rolling target ptr

#pragma unroll 1
        for (int i = 0; i < RPT - 1; i++) {
            const int r = r0 + i;
            unsigned long long mp;
            if (pass == 0) {
                mp = build_mask(cpx, tpx);
                mk[i * TPB + tid] = mp;          // private slot, no barrier needed
            } else {
                mp = mk[i * TPB + tid];
            }
            // full next-row prefetch (8 independent LDG.128 in flight)
            float N[8][4];
#pragma unroll
            for (int c = 0; c < 8; c++) {
                float4 x = ld4(px + WW + c * PLANE);
                N[c][0] = sigt(x.x); N[c][1] = sigt(x.y);
                N[c][2] = sigt(x.z); N[c][3] = sigt(x.w);
            }

            contrib += row_votes(Shm, C, N, px, wlo, whi, lane,
                                 r > 0, true, mp, pass);
            // roll
#pragma unroll
            for (int j = 0; j < 3; j++)
#pragma unroll
                for (int p = 0; p < 4; p++) Shm[j][p] = C[5 + j][p];
#pragma unroll
            for (int c = 0; c < 8; c++)
#pragma unroll
                for (int p = 0; p < 4; p++) C[c][p] = N[c][p];
            px  += WW;
            cpx += WW;
            tpx += WW;
        }
        {   // last row of band: next row needs only channels 0..2
            const int r = r0 + RPT - 1;
            unsigned long long mp;
            if (pass == 0) {
                mp = build_mask(cpx, tpx);
                mk[(RPT - 1) * TPB + tid] = mp;
            } else {
                mp = mk[(RPT - 1) * TPB + tid];
            }
            const bool hpok = (r + 1 < HH);
            float Sn[3][4];
            if (hpok) {
#pragma unroll
                for (int c = 0; c < 3; c++) {
                    float4 x = ld4(px + WW + c * PLANE);
                    Sn[c][0] = sigt(x.x); Sn[c][1] = sigt(x.y);
                    Sn[c][2] = sigt(x.z); Sn[c][3] = sigt(x.w);
                }
            } else {
#pragma unroll
                for (int c = 0; c < 3; c++)
#pragma unroll
                    for (int p = 0; p < 4; p++) Sn[c][p] = 0.0f;
            }
            contrib += row_votes(Shm, C, Sn, px, wlo, whi, lane,
                                 true, hpok, mp, pass);
        }
    }

    // block reduction: warp shfl -> smem -> one double atomic per block
#pragma unroll
    for (int o = 16; o > 0; o >>= 1)
        contrib += __shfl_down_sync(0xFFFFFFFFu, contrib, o);
    if (lane == 0) wsum[tid >> 5] = contrib;
    __syncthreads();

    if (tid == 0) {
        float s = 0.0f;
#pragma unroll
        for (int i = 0; i < TPB / 32; i++) s += wsum[i];
        atomicAdd(&g_acc, (double)s);
        __threadfence();
        unsigned old = atomicInc(&g_count, NBLK - 1u);   // wraps to 0 on last
        if (old == NBLK - 1u) {
            unsigned long long raw =
                atomicExch((unsigned long long*)&g_acc, 0ULL);
            out[0] = -(float)__longlong_as_double(raw);
        }
    }
}

extern "C" void kernel_launch(void* const* d_in, const int* in_sizes, int n_in,
                              void* d_out, int out_size) {
    const float* atts   = (const float*)d_in[0];
    const float* dets   = (const float*)d_in[1];
    const float* target = (const float*)d_in[2];
    const float* con    = (const float*)d_in[3];
    float* out = (float*)d_out;

    bicon_loss_kernel<<<NBLK, TPB>>>(atts, dets, target, con, out);
}

// round 12
// speedup vs baseline: 1.0882x; 1.0102x over previous
#include <cuda_runtime.h>
#include <cstdint>

#define BB 8
#define CC 8
#define HH 512
#define WW 512
#define PLANE (HH*WW)                 // 262144
#define PIX   (BB*HH*WW)              // 2097152
#define NEL   (BB*CC*HH*WW)           // 16777216

#define TPB   128                     // threads per block (4 warps, full row)
#define RPT   8                       // rows per thread
#define CPB   (TPB*4)                 // 512 cols per block = whole image row
#define NBX   (WW/CPB)                // 1
#define NBY   (HH/RPT)                // 64
#define NBLK  (NBX*NBY*BB)            // 512

__device__ double       g_acc;        // zero-init; reset by last block each run
__device__ unsigned int g_count;      // wraps to 0 via atomicInc

// sigmoid via single-MUFU tanh.approx: sigma(x) = 0.5 + 0.5*tanh(x/2)
__device__ __forceinline__ float sigt(float x) {
    float t;
    asm("tanh.approx.f32 %0, %1;" : "=f"(t) : "f"(0.5f * x));
    return fmaf(0.5f, t, 0.5f);
}
__device__ __forceinline__ float4 ld4(const float* __restrict__ p) {
    return *reinterpret_cast<const float4*>(p);
}
__device__ __forceinline__ float clog(float x) {
    return fmaxf(__logf(x), -100.0f);   // matches jnp.clip(log(x), -100)
}

// col w0-1 of same row/channel: left lane's a[3]; lane-0 fixup LDG (L1/L2 hit)
__device__ __forceinline__ float getL(const float a[4], const float* __restrict__ g,
                                      bool ok, int lane) {
    float v = __shfl_up_sync(0xffffffffu, a[3], 1);
    if (lane == 0) v = ok ? sigt(__ldg(g)) : 0.0f;
    return v;
}
// col w0+4: right lane's a[0]; lane-31 fixup LDG
__device__ __forceinline__ float getR(const float a[4], const float* __restrict__ g,
                                      bool ok, int lane) {
    float v = __shfl_down_sync(0xffffffffu, a[0], 1);
    if (lane == 31) v = ok ? sigt(__ldg(g)) : 0.0f;
    return v;
}

// con_target bitmasks (4 px x 8 bits) + target bits packed into one u64
__device__ __forceinline__ unsigned long long build_mask(
        const float* __restrict__ cb, const float* __restrict__ tb) {
    unsigned m0 = 0, m1 = 0, m2 = 0, m3 = 0;
#pragma unroll
    for (int c = 0; c < 8; c++) {
        float4 t = ld4(cb + c * PLANE);
        m0 |= ((unsigned)(t.x > 0.5f)) << c;
        m1 |= ((unsigned)(t.y > 0.5f)) << c;
        m2 |= ((unsigned)(t.z > 0.5f)) << c;
        m3 |= ((unsigned)(t.w > 0.5f)) << c;
    }
    float4 tg = ld4(tb);
    unsigned t4 = (unsigned)(tg.x > 0.5f) | ((unsigned)(tg.y > 0.5f) << 1)
                | ((unsigned)(tg.z > 0.5f) << 2) | ((unsigned)(tg.w > 0.5f) << 3);
    return (unsigned long long)(m0 | (m1 << 8) | (m2 << 16) | (m3 << 24))
         | ((unsigned long long)t4 << 32);
}

// votes + loss terms for one row of a 4-pixel strip.
// Shm: ch5,6,7 sigmoids at row r-1; C: all 8 ch at row r; Sn: ch0,1,2 at row r+1.
__device__ __forceinline__ float row_votes(
    const float Shm[3][4], const float C[8][4], const float Sn[3][4],
    const float* __restrict__ px,
    bool wlo, bool whi, int lane, bool hmok, bool hpok,
    unsigned long long mp, int pass)
{
    float L7 = getL(Shm[2], px - WW + 7 * PLANE - 1, hmok && !wlo, lane);
    float R5 = getR(Shm[0], px - WW + 5 * PLANE + 4, hmok && !whi, lane);
    float L4 = getL(C[4],   px      + 4 * PLANE - 1, !wlo,         lane);
    float R3 = getR(C[3],   px      + 3 * PLANE + 4, !whi,         lane);
    float L2 = getL(Sn[2],  px + WW + 2 * PLANE - 1, hpok && !wlo, lane);
    float R0 = getR(Sn[0],  px + WW + 0 * PLANE + 4, hpok && !whi, lane);

    float accb = 0.0f, accp = 0.0f;
#pragma unroll
    for (int p = 0; p < 4; p++) {
        float nb[8];
        nb[0] = (p == 0) ? L7 : Shm[2][p == 0 ? 0 : p - 1];   // c7(r-1, w-1)
        nb[1] = Shm[1][p];                                    // c6(r-1, w)
        nb[2] = (p == 3) ? R5 : Shm[0][p == 3 ? 3 : p + 1];   // c5(r-1, w+1)
        nb[3] = (p == 0) ? L4 : C[4][p == 0 ? 0 : p - 1];     // c4(r,   w-1)
        nb[4] = (p == 3) ? R3 : C[3][p == 3 ? 3 : p + 1];     // c3(r,   w+1)
        nb[5] = (p == 0) ? L2 : Sn[2][p == 0 ? 0 : p - 1];    // c2(r+1, w-1)
        nb[6] = Sn[1][p];                                     // c1(r+1, w)
        nb[7] = (p == 3) ? R0 : Sn[0][p == 3 ? 3 : p + 1];    // c0(r+1, w+1)

        unsigned m = (unsigned)(mp >> (8 * p)) & 0xFFu;
        bool T = (mp >> (32 + p)) & 1ull;

        // fast path: raw products, one log per side; exact fallback when the
        // product underflows/zeros (padded borders) — matches per-term clamp.
        float pA = 1.f, pB = 1.f, glo = 0.f, mn = 1e30f;
#pragma unroll
        for (int k = 0; k < 8; k++) {
            float s = C[k][p];
            float v = s * nb[k];
            glo += v;
            if (pass == 1) mn = fminf(mn, v);
            bool t = (m >> k) & 1u;
            pA *= t ? v : 1.0f - v;
            pB *= t ? s : 1.0f - s;
        }

        float bic, co;
        if (pA >= 1e-37f) {
            bic = __logf(pA);
        } else {                       // rare: border zeros / extreme tails
            bic = 0.0f;
#pragma unroll
            for (int k = 0; k < 8; k++) {
                float v = C[k][p] * nb[k];
                bool t = (m >> k) & 1u;
                bic += clog(t ? v : 1.0f - v);
            }
        }
        if (pB >= 1e-37f) {
            co = __logf(pB);
        } else {
            co = 0.0f;
#pragma unroll
            for (int k = 0; k < 8; k++) {
                float s = C[k][p];
                bool t = (m >> k) & 1u;
                co += clog(t ? s : 1.0f - s);
            }
        }
        accb += 0.2f * bic + 0.8f * co;

        float g = glo * 0.125f;
        float x;
        if (pass == 0) {
            x = T ? g : 1.0f - g;                        // bce_loss1
        } else {
            bool edge = (m != 0u) && (m != 255u);
            float de  = edge ? (1.0f - mn) : g;          // decouple map
            x = T ? de : 1.0f - de;
        }
        accp += clog(x);
    }
    return accb * (1.0f / (float)NEL) + accp * (1.0f / (float)PIX);
}

__global__ void __launch_bounds__(TPB, 4)
bicon_loss_kernel(const float* __restrict__ atts,
                  const float* __restrict__ dets,
                  const float* __restrict__ target,
                  const float* __restrict__ con,
                  float* __restrict__ out)
{
    __shared__ unsigned long long mk[RPT * TPB];   // 8 KB per-thread mask cache
    __shared__ float wsum[TPB / 32];

    const int tid  = threadIdx.x;
    const int lane = tid & 31;
    const int bid  = blockIdx.x;
    const int band  = bid & (NBY - 1);
    const int b     = bid / NBY;
    const int w0 = tid * 4;                 // full row per block (NBX == 1)
    const int r0 = band * RPT;
    const bool wlo = (w0 == 0), whi = (w0 + 4 == WW);

    const size_t bst  = (size_t)CC * PLANE;
    const size_t soff = (size_t)r0 * WW + w0;   // strip offset within batch image

    float contrib = 0.0f;

#pragma unroll 1
    for (int pass = 0; pass < 2; pass++) {
        const float* px = (pass ? dets : atts) + (size_t)b * bst + soff;

        // prologue: row r0-1 channels 5..7; row r0 all 8
        float Shm[3][4];
        if (r0 > 0) {
#pragma unroll
            for (int j = 0; j < 3; j++) {
                float4 x = ld4(px - WW + (5 + j) * PLANE);
                Shm[j][0] = sigt(x.x); Shm[j][1] = sigt(x.y);
                Shm[j][2] = sigt(x.z); Shm[j][3] = sigt(x.w);
            }
        } else {
#pragma unroll
            for (int j = 0; j < 3; j++)
#pragma unroll
                for (int p = 0; p < 4; p++) Shm[j][p] = 0.0f;
        }
        float C[8][4];
#pragma unroll
        for (int c = 0; c < 8; c++) {
            float4 x = ld4(px + c * PLANE);
            C[c][0] = sigt(x.x); C[c][1] = sigt(x.y);
            C[c][2] = sigt(x.z); C[c][3] = sigt(x.w);
        }

        const float* cpx = con + (size_t)b * bst + soff;       // rolling con ptr
        const float* tpx = target + (size_t)b * PLANE + soff;  // rolling target ptr

#pragma unroll 1
        for (int i = 0; i < RPT - 1; i++) {
            const int r = r0 + i;
            unsigned long long mp;
            if (pass == 0) {
                mp = build_mask(cpx, tpx);
                mk[i * TPB + tid] = mp;          // private slot, no barrier needed
            } else {
                mp = mk[i * TPB + tid];
            }
            // full next-row prefetch (8 independent LDG.128 in flight)
            float N[8][4];
#pragma unroll
            for (int c = 0; c < 8; c++) {
                float4 x = ld4(px + WW + c * PLANE);
                N[c][0] = sigt(x.x); N[c][1] = sigt(x.y);
                N[c][2] = sigt(x.z); N[c][3] = sigt(x.w);
            }

            contrib += row_votes(Shm, C, N, px, wlo, whi, lane,
                                 r > 0, true, mp, pass);
            // roll
#pragma unroll
            for (int j = 0; j < 3; j++)
#pragma unroll
                for (int p = 0; p < 4; p++) Shm[j][p] = C[5 + j][p];
#pragma unroll
            for (int c = 0; c < 8; c++)
#pragma unroll
                for (int p = 0; p < 4; p++) C[c][p] = N[c][p];
            px  += WW;
            cpx += WW;
            tpx += WW;
        }
        {   // last row of band: next row needs only channels 0..2
            const int r = r0 + RPT - 1;
            unsigned long long mp;
            if (pass == 0) {
                mp = build_mask(cpx, tpx);
                mk[(RPT - 1) * TPB + tid] = mp;
            } else {
                mp = mk[(RPT - 1) * TPB + tid];
            }
            const bool hpok = (r + 1 < HH);
            float Sn[3][4];
            if (hpok) {
#pragma unroll
                for (int c = 0; c < 3; c++) {
                    float4 x = ld4(px + WW + c * PLANE);
                    Sn[c][0] = sigt(x.x); Sn[c][1] = sigt(x.y);
                    Sn[c][2] = sigt(x.z); Sn[c][3] = sigt(x.w);
                }
            } else {
#pragma unroll
                for (int c = 0; c < 3; c++)
#pragma unroll
                    for (int p = 0; p < 4; p++) Sn[c][p] = 0.0f;
            }
            contrib += row_votes(Shm, C, Sn, px, wlo, whi, lane,
                                 true, hpok, mp, pass);
        }
    }

    // block reduction: warp shfl -> smem -> one double atomic per block
#pragma unroll
    for (int o = 16; o > 0; o >>= 1)
        contrib += __shfl_down_sync(0xFFFFFFFFu, contrib, o);
    if (lane == 0) wsum[tid >> 5] = contrib;
    __syncthreads();

    if (tid == 0) {
        float s = 0.0f;
#pragma unroll
        for (int i = 0; i < TPB / 32; i++) s += wsum[i];
        atomicAdd(&g_acc, (double)s);
        __threadfence();
        unsigned old = atomicInc(&g_count, NBLK - 1u);   // wraps to 0 on last
        if (old == NBLK - 1u) {
            unsigned long long raw =
                atomicExch((unsigned long long*)&g_acc, 0ULL);
            out[0] = -(float)__longlong_as_double(raw);
        }
    }
}

extern "C" void kernel_launch(void* const* d_in, const int* in_sizes, int n_in,
                              void* d_out, int out_size) {
    const float* atts   = (const float*)d_in[0];
    const float* dets   = (const float*)d_in[1];
    const float* target = (const float*)d_in[2];
    const float* con    = (const float*)d_in[3];
    float* out = (float*)d_out;

    bicon_loss_kernel<<<NBLK, TPB>>>(atts, dets, target, con, out);
}